// round 1
// baseline (speedup 1.0000x reference)
#include <cuda_runtime.h>

#define HW 784
#define IMG_W 28

// Scratch (allocation-free rule: __device__ globals)
__device__ float g_y1 [32u * 256u * 784u];   // conv1 output
__device__ float g_y1s[32u * 256u * 784u];   // shuffled conv1 output
__device__ float g_y2 [32u * 256u * 784u];   // 3x3 conv output

// ---------------------------------------------------------------------------
// Tiled GEMM for 1x1 convs:  C[b][m][n] = act( sum_k A[m][k] * B[b][k][n] [+ res] )
// A: [M,K] row-major weights. B: per-batch [K, 784]. Tiles 128x128x8, 256 thr,
// 8x8 per-thread accumulators.
// RESID: adds x[b][m][ perm[m][n] ] before activation (conv3 epilogue).
// ---------------------------------------------------------------------------
template <bool RELU, bool RESID>
__global__ __launch_bounds__(256)
void gemm1x1_kernel(const float* __restrict__ A,
                    const float* __restrict__ B,
                    float* __restrict__ C,
                    int M, int K,
                    const float* __restrict__ xres,
                    const int* __restrict__ perm)
{
    __shared__ float As[8][128];
    __shared__ float Bs[8][128];

    const int tid   = threadIdx.x;
    const int b     = blockIdx.z;
    const int mtile = blockIdx.y * 128;
    const int ntile = blockIdx.x * 128;

    const float* Bb = B + (size_t)b * K * HW;

    const int arow  = tid >> 1;          // 0..127
    const int acol  = (tid & 1) * 4;     // 0 or 4
    const int bkrow = tid >> 5;          // 0..7
    const int bncol = (tid & 31) * 4;    // 0..124

    const int tm = (tid / 16) * 8;
    const int tn = (tid % 16) * 8;

    float acc[8][8];
#pragma unroll
    for (int i = 0; i < 8; i++)
#pragma unroll
        for (int j = 0; j < 8; j++) acc[i][j] = 0.f;

    for (int k0 = 0; k0 < K; k0 += 8) {
        // load A tile (always in-bounds: M % 128 == 0, K % 8 == 0)
        float4 av = *(const float4*)(A + (size_t)(mtile + arow) * K + k0 + acol);
        As[acol + 0][arow] = av.x;
        As[acol + 1][arow] = av.y;
        As[acol + 2][arow] = av.z;
        As[acol + 3][arow] = av.w;

        // load B tile (N guard: 784 % 4 == 0, so float4 all-or-nothing)
        int n = ntile + bncol;
        float4 bv = make_float4(0.f, 0.f, 0.f, 0.f);
        if (n < HW)
            bv = *(const float4*)(Bb + (size_t)(k0 + bkrow) * HW + n);
        *(float4*)&Bs[bkrow][bncol] = bv;

        __syncthreads();

#pragma unroll
        for (int kk = 0; kk < 8; kk++) {
            float ra[8], rb[8];
#pragma unroll
            for (int i = 0; i < 8; i++) ra[i] = As[kk][tm + i];
#pragma unroll
            for (int j = 0; j < 8; j++) rb[j] = Bs[kk][tn + j];
#pragma unroll
            for (int i = 0; i < 8; i++)
#pragma unroll
                for (int j = 0; j < 8; j++)
                    acc[i][j] = fmaf(ra[i], rb[j], acc[i][j]);
        }
        __syncthreads();
    }

#pragma unroll
    for (int i = 0; i < 8; i++) {
        const int m = mtile + tm + i;
#pragma unroll
        for (int j = 0; j < 8; j++) {
            const int n = ntile + tn + j;
            if (n < HW) {
                float v = acc[i][j];
                if (RESID)
                    v += xres[((size_t)b * M + m) * HW + perm[m * HW + n]];
                if (RELU) v = fmaxf(v, 0.f);
                C[((size_t)b * M + m) * HW + n] = v;
            }
        }
    }
}

// ---------------------------------------------------------------------------
// Implicit-GEMM 3x3 conv (pad=1): C[b][co][hw] = relu( sum_{ci,kh,kw} ... )
// A = wd as [256, 2304] row-major (k = ci*9 + kh*3 + kw). In = g_y1s.
// ---------------------------------------------------------------------------
__global__ __launch_bounds__(256)
void conv3x3_kernel(const float* __restrict__ A,
                    const float* __restrict__ In,
                    float* __restrict__ Out)
{
    const int M = 256, K = 2304;
    __shared__ float As[8][128];
    __shared__ float Bs[8][128];

    const int tid   = threadIdx.x;
    const int b     = blockIdx.z;
    const int mtile = blockIdx.y * 128;
    const int ntile = blockIdx.x * 128;

    const float* Inb = In + (size_t)b * 256 * HW;

    const int arow  = tid >> 1;
    const int acol  = (tid & 1) * 4;
    const int bkrow = tid >> 5;
    const int bncol = (tid & 31) * 4;

    const int tm = (tid / 16) * 8;
    const int tn = (tid % 16) * 8;

    float acc[8][8];
#pragma unroll
    for (int i = 0; i < 8; i++)
#pragma unroll
        for (int j = 0; j < 8; j++) acc[i][j] = 0.f;

    for (int k0 = 0; k0 < K; k0 += 8) {
        float4 av = *(const float4*)(A + (size_t)(mtile + arow) * K + k0 + acol);
        As[acol + 0][arow] = av.x;
        As[acol + 1][arow] = av.y;
        As[acol + 2][arow] = av.z;
        As[acol + 3][arow] = av.w;

        // implicit im2col row: kr -> (ci, kh, kw)
        const int kr  = k0 + bkrow;
        const int ci  = kr / 9;
        const int rr  = kr - ci * 9;
        const int kh  = rr / 3;
        const int kw  = rr - kh * 3;
        const float* row = Inb + (size_t)ci * HW;

#pragma unroll
        for (int e = 0; e < 4; e++) {
            const int hw = ntile + bncol + e;
            float v = 0.f;
            if (hw < HW) {
                const int oh = hw / IMG_W;
                const int ow = hw - oh * IMG_W;
                const int ih = oh + kh - 1;
                const int iw = ow + kw - 1;
                if ((unsigned)ih < IMG_W && (unsigned)iw < IMG_W)
                    v = row[ih * IMG_W + iw];
            }
            Bs[bkrow][bncol + e] = v;
        }

        __syncthreads();

#pragma unroll
        for (int kk = 0; kk < 8; kk++) {
            float ra[8], rb[8];
#pragma unroll
            for (int i = 0; i < 8; i++) ra[i] = As[kk][tm + i];
#pragma unroll
            for (int j = 0; j < 8; j++) rb[j] = Bs[kk][tn + j];
#pragma unroll
            for (int i = 0; i < 8; i++)
#pragma unroll
                for (int j = 0; j < 8; j++)
                    acc[i][j] = fmaf(ra[i], rb[j], acc[i][j]);
        }
        __syncthreads();
    }

#pragma unroll
    for (int i = 0; i < 8; i++) {
        const int m = mtile + tm + i;
#pragma unroll
        for (int j = 0; j < 8; j++) {
            const int n = ntile + tn + j;
            if (n < HW)
                Out[((size_t)b * M + m) * HW + n] = fmaxf(acc[i][j], 0.f);
        }
    }
}

// ---------------------------------------------------------------------------
// Per-channel spatial shuffle: out[b][c][j] = in[b][c][ perm[c][j] ]
// ---------------------------------------------------------------------------
__global__ __launch_bounds__(256)
void shuffle_kernel(const float* __restrict__ in, float* __restrict__ out,
                    const int* __restrict__ perm, int C, long total)
{
    long idx = (long)blockIdx.x * blockDim.x + threadIdx.x;
    const long stride = (long)gridDim.x * blockDim.x;
    for (; idx < total; idx += stride) {
        const int  j   = (int)(idx % HW);
        const long row = idx / HW;
        const int  c   = (int)(row % C);
        out[idx] = in[row * HW + perm[c * HW + j]];
    }
}

// ---------------------------------------------------------------------------
extern "C" void kernel_launch(void* const* d_in, const int* in_sizes, int n_in,
                              void* d_out, int out_size)
{
    const float* x  = (const float*)d_in[0];   // [32,1024,28,28]
    const float* w1 = (const float*)d_in[1];   // [256,1024,1,1]
    const float* wd = (const float*)d_in[2];   // [256,256,3,3]
    const float* w3 = (const float*)d_in[3];   // [1024,256,1,1]
    const int*   pd = (const int*)d_in[4];     // [256,784]
    const int*   pr = (const int*)d_in[5];     // [1024,784]
    float*       out = (float*)d_out;          // [32,1024,28,28]

    float *y1, *y1s, *y2;
    cudaGetSymbolAddress((void**)&y1,  g_y1);
    cudaGetSymbolAddress((void**)&y1s, g_y1s);
    cudaGetSymbolAddress((void**)&y2,  g_y2);

    // 1) conv1 (1x1, 1024->256) + relu
    {
        dim3 grid(7, 2, 32);
        gemm1x1_kernel<true, false><<<grid, 256>>>(w1, x, y1, 256, 1024, nullptr, nullptr);
    }
    // 2) channel shuffle of y1 with perm_dconv
    {
        const long total = 32L * 256 * HW;
        shuffle_kernel<<<4736, 256>>>(y1, y1s, pd, 256, total);
    }
    // 3) 3x3 conv (256->256, pad 1) + relu  (implicit GEMM, K=2304)
    {
        dim3 grid(7, 2, 32);
        conv3x3_kernel<<<grid, 256>>>(wd, y1s, y2);
    }
    // 4) conv3 (1x1, 256->1024) + shuffled residual + relu
    {
        dim3 grid(7, 8, 32);
        gemm1x1_kernel<true, true><<<grid, 256>>>(w3, y2, out, 1024, 256, x, pr);
    }
}

// round 2
// speedup vs baseline: 1.1710x; 1.1710x over previous
#include <cuda_runtime.h>

#define HW 784
#define IMG_W 28
#define NTOT (32 * 784)   // 25088 = 196 * 128
#define ASTRIDE 132       // padded row stride for As (bank-conflict-free STS)

// Scratch (allocation-free rule: __device__ globals)
__device__ float g_y1 [32u * 256u * 784u];   // conv1 output
__device__ float g_y1s[32u * 256u * 784u];   // shuffled conv1 output
__device__ float g_y2 [32u * 256u * 784u];   // 3x3 conv output

// ---------------------------------------------------------------------------
// 1x1 conv as GEMM over fused (batch,spatial) columns.
// C[m][c] = relu( sum_k A[m][k] * B[b(c)][k][n(c)]  [+ res] )
// Tiles 128x128x8, 256 threads, 8x8 per-thread acc, double-buffered smem,
// register prefetch, float4 LDS.
// ---------------------------------------------------------------------------
template <bool RESID>
__global__ __launch_bounds__(256, 2)
void gemm1x1_kernel(const float* __restrict__ A,
                    const float* __restrict__ B,
                    float* __restrict__ C,
                    int M, int K,
                    const float* __restrict__ xres,
                    const int* __restrict__ perm)
{
    __shared__ float As[2][8][ASTRIDE];
    __shared__ float Bs[2][8][128];

    const int tid   = threadIdx.x;
    const int mtile = blockIdx.y * 128;
    const int ctile = blockIdx.x * 128;

    // A loader: one float4 per thread
    const int am = tid >> 1;
    const int ak = (tid & 1) * 4;
    const float* Aptr = A + (size_t)(mtile + am) * K + ak;

    // B loader: one float4 per thread; 4-col group never straddles a batch
    // boundary (784 % 4 == 0) and tile never straddles within a 4-group.
    const int bk   = tid >> 5;
    const int bc4  = (tid & 31) * 4;
    const int bcol = ctile + bc4;
    const int bb   = bcol / HW;
    const int bn   = bcol % HW;
    const float* Bcol = B + (size_t)bb * K * HW + bn;   // + k*HW

    const int tm = (tid >> 4) * 8;
    const int tn = (tid & 15) * 8;

    float acc[8][8];
#pragma unroll
    for (int i = 0; i < 8; i++)
#pragma unroll
        for (int j = 0; j < 8; j++) acc[i][j] = 0.f;

    // prologue: stage k0 = 0 into buffer 0
    float4 aP = *(const float4*)(Aptr);
    float4 bP = *(const float4*)(Bcol + (size_t)bk * HW);
    As[0][ak + 0][am] = aP.x;
    As[0][ak + 1][am] = aP.y;
    As[0][ak + 2][am] = aP.z;
    As[0][ak + 3][am] = aP.w;
    *(float4*)&Bs[0][bk][bc4] = bP;
    __syncthreads();

    int buf = 0;
    for (int k0 = 0; k0 < K; k0 += 8) {
        const bool has_next = (k0 + 8 < K);
        if (has_next) {
            aP = *(const float4*)(Aptr + k0 + 8);
            bP = *(const float4*)(Bcol + (size_t)(k0 + 8 + bk) * HW);
        }

#pragma unroll
        for (int kk = 0; kk < 8; kk++) {
            float4 a0 = *(const float4*)&As[buf][kk][tm];
            float4 a1 = *(const float4*)&As[buf][kk][tm + 4];
            float4 b0 = *(const float4*)&Bs[buf][kk][tn];
            float4 b1 = *(const float4*)&Bs[buf][kk][tn + 4];
            float ra[8] = {a0.x, a0.y, a0.z, a0.w, a1.x, a1.y, a1.z, a1.w};
            float rb[8] = {b0.x, b0.y, b0.z, b0.w, b1.x, b1.y, b1.z, b1.w};
#pragma unroll
            for (int i = 0; i < 8; i++)
#pragma unroll
                for (int j = 0; j < 8; j++)
                    acc[i][j] = fmaf(ra[i], rb[j], acc[i][j]);
        }

        if (has_next) {
            const int nb = buf ^ 1;
            As[nb][ak + 0][am] = aP.x;
            As[nb][ak + 1][am] = aP.y;
            As[nb][ak + 2][am] = aP.z;
            As[nb][ak + 3][am] = aP.w;
            *(float4*)&Bs[nb][bk][bc4] = bP;
        }
        __syncthreads();
        buf ^= 1;
    }

    // epilogue: 8-col groups never straddle a batch boundary (784 % 8 == 0)
    const int c0 = ctile + tn;
    const int ob = c0 / HW;
    const int on = c0 % HW;
#pragma unroll
    for (int i = 0; i < 8; i++) {
        const int m = mtile + tm + i;
        float* crow = C + ((size_t)ob * M + m) * HW + on;
        float v[8];
        if (RESID) {
            const float* xrow = xres + ((size_t)ob * M + m) * HW;
            const int*   prow = perm + (size_t)m * HW;
#pragma unroll
            for (int j = 0; j < 8; j++)
                v[j] = fmaxf(acc[i][j] + xrow[prow[on + j]], 0.f);
        } else {
#pragma unroll
            for (int j = 0; j < 8; j++)
                v[j] = fmaxf(acc[i][j], 0.f);
        }
        *(float4*)(crow + 0) = make_float4(v[0], v[1], v[2], v[3]);
        *(float4*)(crow + 4) = make_float4(v[4], v[5], v[6], v[7]);
    }
}

// ---------------------------------------------------------------------------
// Implicit-GEMM 3x3 conv (pad=1) on pre-shuffled input, same pipeline.
// K = 2304 (ci*9 + kh*3 + kw). B tile gathered with halo/padding predication.
// A 4-wide column group shares (b, oh) and spans ow0..ow0+3 in one image row.
// ---------------------------------------------------------------------------
__global__ __launch_bounds__(256, 2)
void conv3x3_kernel(const float* __restrict__ A,
                    const float* __restrict__ In,
                    float* __restrict__ Out)
{
    const int M = 256, K = 2304;
    __shared__ float As[2][8][ASTRIDE];
    __shared__ float Bs[2][8][128];

    const int tid   = threadIdx.x;
    const int mtile = blockIdx.y * 128;
    const int ctile = blockIdx.x * 128;

    const int am = tid >> 1;
    const int ak = (tid & 1) * 4;
    const float* Aptr = A + (size_t)(mtile + am) * K + ak;

    const int bk   = tid >> 5;
    const int bc4  = (tid & 31) * 4;
    const int bcol = ctile + bc4;
    const int bb   = bcol / HW;
    const int bn0  = bcol % HW;
    const int boh  = bn0 / IMG_W;
    const int bow0 = bn0 % IMG_W;      // multiple of 4, so ow0..ow0+3 < 28
    const float* Inb = In + (size_t)bb * 256 * HW;

    const int tm = (tid >> 4) * 8;
    const int tn = (tid & 15) * 8;

    float acc[8][8];
#pragma unroll
    for (int i = 0; i < 8; i++)
#pragma unroll
        for (int j = 0; j < 8; j++) acc[i][j] = 0.f;

    // gather one B k-row quad for kr
    auto gatherB = [&](int kr, float* v) {
        const int ci = kr / 9;
        const int r9 = kr - ci * 9;
        const int kh = r9 / 3;
        const int kw = r9 - kh * 3;
        const int ih = boh + kh - 1;
        const float* row = Inb + (size_t)ci * HW + ih * IMG_W;
        const bool ihok = (unsigned)ih < (unsigned)IMG_W;
#pragma unroll
        for (int e = 0; e < 4; e++) {
            const int iw = bow0 + kw - 1 + e;
            v[e] = (ihok && (unsigned)iw < (unsigned)IMG_W) ? row[iw] : 0.f;
        }
    };

    float4 aP = *(const float4*)(Aptr);
    float bv[4];
    gatherB(bk, bv);
    As[0][ak + 0][am] = aP.x;
    As[0][ak + 1][am] = aP.y;
    As[0][ak + 2][am] = aP.z;
    As[0][ak + 3][am] = aP.w;
    *(float4*)&Bs[0][bk][bc4] = make_float4(bv[0], bv[1], bv[2], bv[3]);
    __syncthreads();

    int buf = 0;
    for (int k0 = 0; k0 < K; k0 += 8) {
        const bool has_next = (k0 + 8 < K);
        if (has_next) {
            aP = *(const float4*)(Aptr + k0 + 8);
            gatherB(k0 + 8 + bk, bv);
        }

#pragma unroll
        for (int kk = 0; kk < 8; kk++) {
            float4 a0 = *(const float4*)&As[buf][kk][tm];
            float4 a1 = *(const float4*)&As[buf][kk][tm + 4];
            float4 b0 = *(const float4*)&Bs[buf][kk][tn];
            float4 b1 = *(const float4*)&Bs[buf][kk][tn + 4];
            float ra[8] = {a0.x, a0.y, a0.z, a0.w, a1.x, a1.y, a1.z, a1.w};
            float rb[8] = {b0.x, b0.y, b0.z, b0.w, b1.x, b1.y, b1.z, b1.w};
#pragma unroll
            for (int i = 0; i < 8; i++)
#pragma unroll
                for (int j = 0; j < 8; j++)
                    acc[i][j] = fmaf(ra[i], rb[j], acc[i][j]);
        }

        if (has_next) {
            const int nb = buf ^ 1;
            As[nb][ak + 0][am] = aP.x;
            As[nb][ak + 1][am] = aP.y;
            As[nb][ak + 2][am] = aP.z;
            As[nb][ak + 3][am] = aP.w;
            *(float4*)&Bs[nb][bk][bc4] = make_float4(bv[0], bv[1], bv[2], bv[3]);
        }
        __syncthreads();
        buf ^= 1;
    }

    const int c0 = ctile + tn;
    const int ob = c0 / HW;
    const int on = c0 % HW;
#pragma unroll
    for (int i = 0; i < 8; i++) {
        const int m = mtile + tm + i;
        float* crow = Out + ((size_t)ob * M + m) * HW + on;
        *(float4*)(crow + 0) = make_float4(fmaxf(acc[i][0], 0.f), fmaxf(acc[i][1], 0.f),
                                           fmaxf(acc[i][2], 0.f), fmaxf(acc[i][3], 0.f));
        *(float4*)(crow + 4) = make_float4(fmaxf(acc[i][4], 0.f), fmaxf(acc[i][5], 0.f),
                                           fmaxf(acc[i][6], 0.f), fmaxf(acc[i][7], 0.f));
    }
}

// ---------------------------------------------------------------------------
// Per-channel spatial shuffle: out[b][c][j] = in[b][c][ perm[c][j] ]
// ---------------------------------------------------------------------------
__global__ __launch_bounds__(256)
void shuffle_kernel(const float* __restrict__ in, float* __restrict__ out,
                    const int* __restrict__ perm, int C, long total)
{
    long idx = (long)blockIdx.x * blockDim.x + threadIdx.x;
    const long stride = (long)gridDim.x * blockDim.x;
    for (; idx < total; idx += stride) {
        const int  j   = (int)(idx % HW);
        const long row = idx / HW;
        const int  c   = (int)(row % C);
        out[idx] = in[row * HW + perm[c * HW + j]];
    }
}

// ---------------------------------------------------------------------------
extern "C" void kernel_launch(void* const* d_in, const int* in_sizes, int n_in,
                              void* d_out, int out_size)
{
    const float* x  = (const float*)d_in[0];   // [32,1024,28,28]
    const float* w1 = (const float*)d_in[1];   // [256,1024,1,1]
    const float* wd = (const float*)d_in[2];   // [256,256,3,3]
    const float* w3 = (const float*)d_in[3];   // [1024,256,1,1]
    const int*   pd = (const int*)d_in[4];     // [256,784]
    const int*   pr = (const int*)d_in[5];     // [1024,784]
    float*       out = (float*)d_out;          // [32,1024,28,28]

    float *y1, *y1s, *y2;
    cudaGetSymbolAddress((void**)&y1,  g_y1);
    cudaGetSymbolAddress((void**)&y1s, g_y1s);
    cudaGetSymbolAddress((void**)&y2,  g_y2);

    // 1) conv1 (1x1, 1024->256) + relu
    {
        dim3 grid(NTOT / 128, 2);
        gemm1x1_kernel<false><<<grid, 256>>>(w1, x, y1, 256, 1024, nullptr, nullptr);
    }
    // 2) channel shuffle of y1 with perm_dconv
    {
        const long total = 32L * 256 * HW;
        shuffle_kernel<<<4736, 256>>>(y1, y1s, pd, 256, total);
    }
    // 3) 3x3 conv (256->256, pad 1) + relu  (implicit GEMM, K=2304)
    {
        dim3 grid(NTOT / 128, 2);
        conv3x3_kernel<<<grid, 256>>>(wd, y1s, y2);
    }
    // 4) conv3 (1x1, 256->1024) + shuffled residual + relu
    {
        dim3 grid(NTOT / 128, 8);
        gemm1x1_kernel<true><<<grid, 256>>>(w3, y2, out, 1024, 256, x, pr);
    }
}

// round 6
// speedup vs baseline: 2.4624x; 2.1029x over previous
#include <cuda_runtime.h>
#include <cstdint>

#define HW 784
#define IMG_W 28
#define NTOT (32 * 784)      // 25088 = 196 * 128
#define MT 128
#define NT 128
#define KC 32                // K per chunk
#define ROWB 80              // bytes per smem row: 32 bf16 (64B) + 16B pad
#define TILEB (128 * ROWB)   // 10240 B per tile
#define SMEM_BYTES (8 * TILEB)  // 2 bufs x {Ahi,Alo,Bhi,Blo} = 81920 B

// ---------------------------------------------------------------------------
// Scratch
// ---------------------------------------------------------------------------
__device__ float g_y1 [32u * 256u * 784u];
__device__ float g_y1s[32u * 256u * 784u];
__device__ float g_y2 [32u * 256u * 784u];

// ---------------------------------------------------------------------------
// PTX helpers (baseline PTX only: ldmatrix + mma.sync, both sm_80+)
// ---------------------------------------------------------------------------
__device__ __forceinline__ uint32_t smem_to_u32(const void* p) {
    uint32_t a;
    asm("{ .reg .u64 t; cvta.to.shared.u64 t, %1; cvt.u32.u64 %0, t; }" : "=r"(a) : "l"(p));
    return a;
}

__device__ __forceinline__ void ldsm4(uint32_t* r, uint32_t a) {
    asm volatile("ldmatrix.sync.aligned.m8n8.x4.shared.b16 {%0,%1,%2,%3}, [%4];"
                 : "=r"(r[0]), "=r"(r[1]), "=r"(r[2]), "=r"(r[3]) : "r"(a));
}

__device__ __forceinline__ void mma_bf16(float* d, const uint32_t* a, const uint32_t* b) {
    asm volatile(
        "mma.sync.aligned.m16n8k16.row.col.f32.bf16.bf16.f32 "
        "{%0,%1,%2,%3}, {%4,%5,%6,%7}, {%8,%9}, {%0,%1,%2,%3};"
        : "+f"(d[0]), "+f"(d[1]), "+f"(d[2]), "+f"(d[3])
        : "r"(a[0]), "r"(a[1]), "r"(a[2]), "r"(a[3]), "r"(b[0]), "r"(b[1]));
}

// pack two floats -> bf16x2 word (lo half = a, hi half = b)
__device__ __forceinline__ uint32_t pack_bf16x2(float a, float b) {
    uint32_t r;
    asm("cvt.rn.bf16x2.f32 %0, %1, %2;" : "=r"(r) : "f"(b), "f"(a));
    return r;
}

// convert 16 consecutive-k floats -> 8 hi words + 8 lo words, store 2x uint4 each
__device__ __forceinline__ void cvt_store16(char* smem, uint32_t hioff, uint32_t looff,
                                            const float* v) {
    uint32_t hw_[8], lw_[8];
#pragma unroll
    for (int p = 0; p < 8; p++) {
        float a = v[2 * p], b = v[2 * p + 1];
        uint32_t h = pack_bf16x2(a, b);
        float ha = __uint_as_float(h << 16);
        float hb = __uint_as_float(h & 0xFFFF0000u);
        hw_[p] = h;
        lw_[p] = pack_bf16x2(a - ha, b - hb);
    }
    *(uint4*)(smem + hioff)      = make_uint4(hw_[0], hw_[1], hw_[2], hw_[3]);
    *(uint4*)(smem + hioff + 16) = make_uint4(hw_[4], hw_[5], hw_[6], hw_[7]);
    *(uint4*)(smem + looff)      = make_uint4(lw_[0], lw_[1], lw_[2], lw_[3]);
    *(uint4*)(smem + looff + 16) = make_uint4(lw_[4], lw_[5], lw_[6], lw_[7]);
}

__device__ __forceinline__ uint32_t tile_off(int buf, int t) {
    return (uint32_t)(buf * 4 + t) * TILEB;   // t: 0=Ahi 1=Alo 2=Bhi 3=Blo
}

// ---------------------------------------------------------------------------
// Tensor-core conv kernel (warp mma.sync, bf16 split x3, fp32 accum).
// MODE 0: 1x1 conv (B[n][k] = In[b][k][hw]).  MODE 1: 3x3 implicit im2col.
// RESID: fused shuffled-residual + relu epilogue; else plain relu.
// 256 thr = 8 warps (4 M x 2 N), warp tile 32x64, CTA tile 128x128, KC=32.
// ---------------------------------------------------------------------------
template <int MODE, bool RESID>
__global__ void __launch_bounds__(256)
conv_mma_kernel(const float* __restrict__ W, const float* __restrict__ In,
                float* __restrict__ Out, int Mout, int Cin, int KTOT,
                const float* __restrict__ xres, const int* __restrict__ perm)
{
    extern __shared__ char smem[];
    const uint32_t sb = smem_to_u32(smem);
    const int tid  = threadIdx.x;
    const int wid  = tid >> 5;
    const int lane = tid & 31;
    const int mtile = blockIdx.y * MT;
    const int ctile = blockIdx.x * NT;

    // ---- loader mapping: 128 rows x 2 k-halves of 16 ----
    const int lr = tid & 127;
    const int kh = (tid >> 7) * 16;            // k offset within chunk
    const uint32_t stoff = (uint32_t)lr * ROWB + (uint32_t)kh * 2;

    const float* Arow = W + (size_t)(mtile + lr) * KTOT + kh;

    const int coln = ctile + lr;
    const int bb   = coln / HW;
    const int hwn  = coln - bb * HW;
    const int boh  = hwn / IMG_W;
    const int bow  = hwn - boh * IMG_W;
    const float* Bb = In + (size_t)bb * Cin * HW;

    // ---- mma fragment addressing ----
    const int warpM = (wid >> 1) * 32;
    const int warpN = (wid & 1) * 64;
    // A frag (m16k16): lanes 0-7 rows m0-7@k0, 8-15 m8-15@k0, 16-23 m0-7@k8, 24-31 m8-15@k8
    const uint32_t aRowOff = (uint32_t)(warpM + (lane & 7) + ((lane >> 3) & 1) * 8) * ROWB
                           + ((lane >> 4) & 1) * 16;
    // B frag pair (two n8 tiles): lanes 0-7 n0-7@k0, 8-15 n0-7@k8, 16-23 n8-15@k0, 24-31 n8-15@k8
    const uint32_t bRowOff = (uint32_t)(warpN + (lane & 7) + ((lane >> 4) & 1) * 8) * ROWB
                           + ((lane >> 3) & 1) * 16;

    float acc[2][8][4];
#pragma unroll
    for (int i = 0; i < 2; i++)
#pragma unroll
        for (int j = 0; j < 8; j++)
#pragma unroll
            for (int q = 0; q < 4; q++) acc[i][j][q] = 0.f;

    const int NCH = KTOT / KC;

    // ---- B gather (16 consecutive k elements starting at k0+kh) ----
    auto loadB = [&](int k0, float* v) {
        if (MODE == 0) {
#pragma unroll
            for (int e = 0; e < 16; e++)
                v[e] = Bb[(size_t)(k0 + kh + e) * HW + hwn];
        } else {
#pragma unroll
            for (int e = 0; e < 16; e++) {
                const int k  = k0 + kh + e;
                const int ci = k / 9;
                const int r9 = k - ci * 9;
                const int kk = r9 / 3;
                const int kw = r9 - kk * 3;
                const int ih = boh + kk - 1;
                const int iw = bow + kw - 1;
                float x = 0.f;
                if ((unsigned)ih < (unsigned)IMG_W && (unsigned)iw < (unsigned)IMG_W)
                    x = Bb[(size_t)ci * HW + ih * IMG_W + iw];
                v[e] = x;
            }
        }
    };
    auto loadA = [&](int k0, float* v) {
#pragma unroll
        for (int j = 0; j < 4; j++)
            *(float4*)(v + j * 4) = *(const float4*)(Arow + k0 + j * 4);
    };

    // ---- prologue: chunk 0 -> buf 0 ----
    {
        float va[16], vb[16];
        loadA(0, va);
        loadB(0, vb);
        cvt_store16(smem, tile_off(0, 0) + stoff, tile_off(0, 1) + stoff, va);
        cvt_store16(smem, tile_off(0, 2) + stoff, tile_off(0, 3) + stoff, vb);
    }
    __syncthreads();

    for (int c = 0; c < NCH; c++) {
        const int buf = c & 1;
        float va[16], vb[16];
        const bool nxt = (c + 1 < NCH);
        if (nxt) {
            loadA((c + 1) * KC, va);
            loadB((c + 1) * KC, vb);
        }

        // ---- compute chunk c from smem[buf] ----
        const uint32_t aHi = sb + tile_off(buf, 0);
        const uint32_t aLo = sb + tile_off(buf, 1);
        const uint32_t bHi = sb + tile_off(buf, 2);
        const uint32_t bLo = sb + tile_off(buf, 3);
#pragma unroll
        for (int ks = 0; ks < 2; ks++) {
            uint32_t ah[8], al[8];
            ldsm4(ah + 0, aHi + aRowOff + ks * 32);
            ldsm4(ah + 4, aHi + aRowOff + 16 * ROWB + ks * 32);
            ldsm4(al + 0, aLo + aRowOff + ks * 32);
            ldsm4(al + 4, aLo + aRowOff + 16 * ROWB + ks * 32);
#pragma unroll
            for (int np = 0; np < 4; np++) {
                uint32_t bh[4], bl[4];
                ldsm4(bh, bHi + bRowOff + np * 16 * ROWB + ks * 32);
                ldsm4(bl, bLo + bRowOff + np * 16 * ROWB + ks * 32);
#pragma unroll
                for (int mf = 0; mf < 2; mf++)
#pragma unroll
                    for (int t = 0; t < 2; t++) {
                        float* C = acc[mf][np * 2 + t];
                        mma_bf16(C, ah + mf * 4, bh + t * 2);
                        mma_bf16(C, ah + mf * 4, bl + t * 2);
                        mma_bf16(C, al + mf * 4, bh + t * 2);
                    }
            }
        }

        if (nxt) {
            const int nb = buf ^ 1;
            cvt_store16(smem, tile_off(nb, 0) + stoff, tile_off(nb, 1) + stoff, va);
            cvt_store16(smem, tile_off(nb, 2) + stoff, tile_off(nb, 3) + stoff, vb);
        }
        __syncthreads();
    }

    // ---- epilogue: C frags -> gmem (float2 stores), fused relu/residual ----
    const int mBase = mtile + warpM + (lane >> 2);
    const int nCol  = ctile + warpN + (lane & 3) * 2;
#pragma unroll
    for (int mf = 0; mf < 2; mf++) {
#pragma unroll
        for (int nf = 0; nf < 8; nf++) {
            const float* C = acc[mf][nf];
            const int n  = nCol + nf * 8;
            const int b2 = n / HW;
            const int hw = n - b2 * HW;
            const int m0 = mBase + mf * 16;
            const int m1 = m0 + 8;
            float v0 = C[0], v1 = C[1], v2 = C[2], v3 = C[3];
            if (RESID) {
                const float* xr0 = xres + ((size_t)b2 * Mout + m0) * HW;
                const float* xr1 = xres + ((size_t)b2 * Mout + m1) * HW;
                const int* p0 = perm + (size_t)m0 * HW + hw;
                const int* p1 = perm + (size_t)m1 * HW + hw;
                v0 += xr0[p0[0]]; v1 += xr0[p0[1]];
                v2 += xr1[p1[0]]; v3 += xr1[p1[1]];
            }
            v0 = fmaxf(v0, 0.f); v1 = fmaxf(v1, 0.f);
            v2 = fmaxf(v2, 0.f); v3 = fmaxf(v3, 0.f);
            *(float2*)(Out + ((size_t)b2 * Mout + m0) * HW + hw) = make_float2(v0, v1);
            *(float2*)(Out + ((size_t)b2 * Mout + m1) * HW + hw) = make_float2(v2, v3);
        }
    }
}

// ---------------------------------------------------------------------------
// Per-channel spatial shuffle: out[b][c][j] = in[b][c][ perm[c][j] ]
// ---------------------------------------------------------------------------
__global__ __launch_bounds__(256)
void shuffle_kernel(const float* __restrict__ in, float* __restrict__ out,
                    const int* __restrict__ perm, int C, long total)
{
    long idx = (long)blockIdx.x * blockDim.x + threadIdx.x;
    const long stride = (long)gridDim.x * blockDim.x;
    for (; idx < total; idx += stride) {
        const int  j   = (int)(idx % HW);
        const long row = idx / HW;
        const int  c   = (int)(row % C);
        out[idx] = in[row * HW + perm[c * HW + j]];
    }
}

// ---------------------------------------------------------------------------
extern "C" void kernel_launch(void* const* d_in, const int* in_sizes, int n_in,
                              void* d_out, int out_size)
{
    const float* x  = (const float*)d_in[0];   // [32,1024,28,28]
    const float* w1 = (const float*)d_in[1];   // [256,1024,1,1]
    const float* wd = (const float*)d_in[2];   // [256,256,3,3]
    const float* w3 = (const float*)d_in[3];   // [1024,256,1,1]
    const int*   pd = (const int*)d_in[4];     // [256,784]
    const int*   pr = (const int*)d_in[5];     // [1024,784]
    float*       out = (float*)d_out;          // [32,1024,28,28]

    float *y1, *y1s, *y2;
    cudaGetSymbolAddress((void**)&y1,  g_y1);
    cudaGetSymbolAddress((void**)&y1s, g_y1s);
    cudaGetSymbolAddress((void**)&y2,  g_y2);

    cudaFuncSetAttribute(conv_mma_kernel<0, false>,
                         cudaFuncAttributeMaxDynamicSharedMemorySize, SMEM_BYTES);
    cudaFuncSetAttribute(conv_mma_kernel<1, false>,
                         cudaFuncAttributeMaxDynamicSharedMemorySize, SMEM_BYTES);
    cudaFuncSetAttribute(conv_mma_kernel<0, true>,
                         cudaFuncAttributeMaxDynamicSharedMemorySize, SMEM_BYTES);

    // 1) conv1 (1x1, 1024->256) + relu
    {
        dim3 grid(NTOT / NT, 256 / MT);
        conv_mma_kernel<0, false><<<grid, 256, SMEM_BYTES>>>(
            w1, x, y1, 256, 1024, 1024, nullptr, nullptr);
    }
    // 2) channel shuffle of y1 with perm_dconv
    {
        const long total = 32L * 256 * HW;
        shuffle_kernel<<<4736, 256>>>(y1, y1s, pd, 256, total);
    }
    // 3) 3x3 conv (256->256, pad 1) + relu  (implicit GEMM, K=2304)
    {
        dim3 grid(NTOT / NT, 256 / MT);
        conv_mma_kernel<1, false><<<grid, 256, SMEM_BYTES>>>(
            wd, y1s, y2, 256, 256, 2304, nullptr, nullptr);
    }
    // 4) conv3 (1x1, 256->1024) + shuffled residual + relu
    {
        dim3 grid(NTOT / NT, 1024 / MT);
        conv_mma_kernel<0, true><<<grid, 256, SMEM_BYTES>>>(
            w3, y2, out, 1024, 256, 256, x, pr);
    }
}

// round 8
// speedup vs baseline: 3.2135x; 1.3050x over previous
#include <cuda_runtime.h>
#include <cstdint>

#define HW 784
#define IMG_W 28
#define NTOT (32 * 784)     // 25088 = 196 * 128
#define MT 128
#define NT 128

// ---------------------------------------------------------------------------
// Scratch (__device__ globals; allocation-free rule)
// ---------------------------------------------------------------------------
__device__ float    g_y1  [32u * 256u * 784u];       // conv1 out (fp32, relu)
__device__ uint16_t g_xh  [32u * 1024u * 784u];      // x split hi
__device__ uint16_t g_xl  [32u * 1024u * 784u];      // x split lo
__device__ uint16_t g_w1h [256u * 1024u], g_w1l[256u * 1024u];
__device__ uint16_t g_wdh [256u * 2304u], g_wdl[256u * 2304u];   // K-reordered
__device__ uint16_t g_w3h [1024u * 256u], g_w3l[1024u * 256u];
__device__ uint16_t g_y1th[32u * 784u * 256u], g_y1tl[32u * 784u * 256u]; // shuffled, transposed
__device__ uint16_t g_y2h [32u * 256u * 784u], g_y2l[32u * 256u * 784u]; // dconv out

// ---------------------------------------------------------------------------
// PTX helpers (sm_80+ baseline only)
// ---------------------------------------------------------------------------
__device__ __forceinline__ uint32_t smem_to_u32(const void* p) {
    uint32_t a;
    asm("{ .reg .u64 t; cvta.to.shared.u64 t, %1; cvt.u32.u64 %0, t; }" : "=r"(a) : "l"(p));
    return a;
}
__device__ __forceinline__ void ldsm4(uint32_t* r, uint32_t a) {
    asm volatile("ldmatrix.sync.aligned.m8n8.x4.shared.b16 {%0,%1,%2,%3}, [%4];"
                 : "=r"(r[0]), "=r"(r[1]), "=r"(r[2]), "=r"(r[3]) : "r"(a));
}
__device__ __forceinline__ void ldsm4t(uint32_t* r, uint32_t a) {
    asm volatile("ldmatrix.sync.aligned.m8n8.x4.trans.shared.b16 {%0,%1,%2,%3}, [%4];"
                 : "=r"(r[0]), "=r"(r[1]), "=r"(r[2]), "=r"(r[3]) : "r"(a));
}
__device__ __forceinline__ void mma_bf16(float* d, const uint32_t* a, const uint32_t* b) {
    asm volatile(
        "mma.sync.aligned.m16n8k16.row.col.f32.bf16.bf16.f32 "
        "{%0,%1,%2,%3}, {%4,%5,%6,%7}, {%8,%9}, {%0,%1,%2,%3};"
        : "+f"(d[0]), "+f"(d[1]), "+f"(d[2]), "+f"(d[3])
        : "r"(a[0]), "r"(a[1]), "r"(a[2]), "r"(a[3]), "r"(b[0]), "r"(b[1]));
}
__device__ __forceinline__ uint32_t pack_bf16x2(float a, float b) {
    uint32_t r;
    asm("cvt.rn.bf16x2.f32 %0, %1, %2;" : "=r"(r) : "f"(b), "f"(a));
    return r;
}
__device__ __forceinline__ void cpa16(uint32_t dst, const void* src, int sz) {
    asm volatile("cp.async.ca.shared.global [%0], [%1], 16, %2;"
                 :: "r"(dst), "l"(src), "r"(sz));
}
#define CP_COMMIT() asm volatile("cp.async.commit_group;" ::)
#define CP_WAIT1()  asm volatile("cp.async.wait_group 1;" ::)
#define CP_WAIT0()  asm volatile("cp.async.wait_group 0;" ::)

// ---------------------------------------------------------------------------
// GEMM kernel: operands pre-split to hi/lo bf16 in gmem. cp.async pipeline.
// MODE 0: B = [b][k][hw] (1x1 conv), [k][n] smem rows + ldmatrix.trans.
// MODE 1: B = y1t [b][hw][256] (3x3 conv, K = (kh,kw)*256+ci), [n][k] smem rows.
// OUT 0: fp32 relu -> OutF.  OUT 1: hi/lo bf16 relu -> OutH/OutL.
// OUT 2: fp32 + shuffled residual + relu -> OutF.
// ---------------------------------------------------------------------------
template <int MODE, int OUT>
__global__ void __launch_bounds__(256, 2)
conv_mma2(const uint16_t* __restrict__ Ah, const uint16_t* __restrict__ Al,
          const uint16_t* __restrict__ Bh, const uint16_t* __restrict__ Bl,
          float* __restrict__ OutF, uint16_t* __restrict__ OutH, uint16_t* __restrict__ OutL,
          int Mout, int KTOT,
          const float* __restrict__ xres, const int* __restrict__ perm)
{
    extern __shared__ char smem[];
    const uint32_t sb = smem_to_u32(smem);
    const int tid = threadIdx.x, wid = tid >> 5, lane = tid & 31;
    const int mtile = blockIdx.y * MT, ctile = blockIdx.x * NT;

    constexpr int BTILEB = (MODE == 0) ? (32 * 272) : (128 * 80);
    constexpr int STAGE  = 2 * 10240 + 2 * BTILEB;

    // ---- A loader: 128 rows x 64B; thread t: row t>>1, 32B part t&1 ----
    const int arow = tid >> 1, apart = tid & 1;
    const uint16_t* aSrcH = Ah + (size_t)(mtile + arow) * KTOT + apart * 16;
    const uint16_t* aSrcL = Al + (size_t)(mtile + arow) * KTOT + apart * 16;
    const uint32_t aDst = (uint32_t)arow * 80 + apart * 32;

    // ---- B loader precompute ----
    int brow = 0, bsc0 = 0;
    size_t bOff0 = 0, bOff1 = 0;
    int nrow = 0, bpart = 0, boh = 0, bow = 0;
    size_t bBase = 0;
    if (MODE == 0) {
        brow = tid >> 3; bsc0 = (tid & 7) * 2;
        const int col0 = ctile + bsc0 * 8, col1 = col0 + 8;
        const int bb0 = col0 / HW, hw0 = col0 - bb0 * HW;
        const int bb1 = col1 / HW, hw1 = col1 - bb1 * HW;
        bOff0 = ((size_t)bb0 * KTOT + brow) * HW + hw0;
        bOff1 = ((size_t)bb1 * KTOT + brow) * HW + hw1;
    } else {
        nrow = tid >> 1; bpart = tid & 1;
        const int coln = ctile + nrow;
        const int bbn = coln / HW, hwn = coln - bbn * HW;
        boh = hwn / IMG_W; bow = hwn - boh * IMG_W;
        bBase = (size_t)bbn * HW * 256;
    }

    auto issue = [&](int c, int buf) {
        const uint32_t s0 = sb + buf * STAGE;
        // A hi/lo
        {
            const uint16_t* ph = aSrcH + (size_t)c * 32;
            const uint16_t* pl = aSrcL + (size_t)c * 32;
            const uint32_t d = s0 + aDst;
            cpa16(d, ph, 16);           cpa16(d + 16, ph + 8, 16);
            cpa16(d + 10240, pl, 16);   cpa16(d + 10240 + 16, pl + 8, 16);
        }
        if (MODE == 0) {
            const size_t kadd = (size_t)c * 32 * HW;
            const uint32_t d = s0 + 20480 + (uint32_t)brow * 272 + bsc0 * 16;
            cpa16(d,              Bh + bOff0 + kadd, 16);
            cpa16(d + 16,         Bh + bOff1 + kadd, 16);
            cpa16(d + BTILEB,      Bl + bOff0 + kadd, 16);
            cpa16(d + BTILEB + 16, Bl + bOff1 + kadd, 16);
        } else {
            const int khkw = c >> 3, cib = (c & 7) * 32;
            const int kh = khkw / 3, kw = khkw - kh * 3;
            const int ih = boh + kh - 1, iw = bow + kw - 1;
            const bool ok = ((unsigned)ih < (unsigned)IMG_W) && ((unsigned)iw < (unsigned)IMG_W);
            const int sz = ok ? 16 : 0;
            const size_t off = ok ? (bBase + (size_t)(ih * IMG_W + iw) * 256 + cib + bpart * 16) : 0;
            const uint32_t d = s0 + 20480 + (uint32_t)nrow * 80 + bpart * 32;
            cpa16(d,              Bh + off,     sz);
            cpa16(d + 16,         Bh + off + 8, sz);
            cpa16(d + BTILEB,      Bl + off,     sz);
            cpa16(d + BTILEB + 16, Bl + off + 8, sz);
        }
    };

    // ---- fragment addressing ----
    const int warpM = (wid >> 1) * 32, warpN = (wid & 1) * 64;
    const uint32_t aRowOff = (uint32_t)(warpM + (lane & 7) + ((lane >> 3) & 1) * 8) * 80
                           + ((lane >> 4) & 1) * 16;
    uint32_t bFragOff;
    if (MODE == 0)
        bFragOff = (uint32_t)(lane & 15) * 272 + (uint32_t)(warpN + (lane >> 4) * 8) * 2;
    else
        bFragOff = (uint32_t)(warpN + (lane & 7) + ((lane >> 4) & 1) * 8) * 80
                 + ((lane >> 3) & 1) * 16;

    float acc[2][8][4];
#pragma unroll
    for (int i = 0; i < 2; i++)
#pragma unroll
        for (int j = 0; j < 8; j++)
#pragma unroll
            for (int q = 0; q < 4; q++) acc[i][j][q] = 0.f;

    const int NCH = KTOT / 32;

    issue(0, 0); CP_COMMIT();

    for (int c = 0; c < NCH; c++) {
        const int buf = c & 1;
        if (c + 1 < NCH) { issue(c + 1, buf ^ 1); CP_COMMIT(); CP_WAIT1(); }
        else             { CP_WAIT0(); }
        __syncthreads();

        const uint32_t aH = sb + buf * STAGE, aL = aH + 10240;
        const uint32_t bH = sb + buf * STAGE + 20480, bL = bH + BTILEB;
#pragma unroll
        for (int ks = 0; ks < 2; ks++) {
            uint32_t ah[8], al[8];
            ldsm4(ah + 0, aH + aRowOff + ks * 32);
            ldsm4(ah + 4, aH + aRowOff + 16 * 80 + ks * 32);
            ldsm4(al + 0, aL + aRowOff + ks * 32);
            ldsm4(al + 4, aL + aRowOff + 16 * 80 + ks * 32);
#pragma unroll
            for (int np = 0; np < 4; np++) {
                uint32_t bh[4], bl[4];
                if (MODE == 0) {
                    const uint32_t o = bFragOff + ks * 16 * 272 + np * 32;
                    ldsm4t(bh, bH + o);
                    ldsm4t(bl, bL + o);
                } else {
                    const uint32_t o = bFragOff + np * 16 * 80 + ks * 32;
                    ldsm4(bh, bH + o);
                    ldsm4(bl, bL + o);
                }
#pragma unroll
                for (int mf = 0; mf < 2; mf++)
#pragma unroll
                    for (int t = 0; t < 2; t++) {
                        float* C = acc[mf][np * 2 + t];
                        mma_bf16(C, ah + mf * 4, bh + t * 2);
                        mma_bf16(C, ah + mf * 4, bl + t * 2);
                        mma_bf16(C, al + mf * 4, bh + t * 2);
                    }
            }
        }
        __syncthreads();
    }

    // ---- epilogue ----
    const int mBase = mtile + warpM + (lane >> 2);
    const int nCol  = ctile + warpN + (lane & 3) * 2;
#pragma unroll
    for (int mf = 0; mf < 2; mf++) {
#pragma unroll
        for (int nf = 0; nf < 8; nf++) {
            const float* C = acc[mf][nf];
            const int n  = nCol + nf * 8;
            const int b2 = n / HW;
            const int hw = n - b2 * HW;
            const int m0 = mBase + mf * 16;
            const int m1 = m0 + 8;
            float v0 = C[0], v1 = C[1], v2 = C[2], v3 = C[3];
            if (OUT == 2) {
                const float* xr0 = xres + ((size_t)b2 * Mout + m0) * HW;
                const float* xr1 = xres + ((size_t)b2 * Mout + m1) * HW;
                const int* p0 = perm + (size_t)m0 * HW + hw;
                const int* p1 = perm + (size_t)m1 * HW + hw;
                v0 += xr0[p0[0]]; v1 += xr0[p0[1]];
                v2 += xr1[p1[0]]; v3 += xr1[p1[1]];
            }
            v0 = fmaxf(v0, 0.f); v1 = fmaxf(v1, 0.f);
            v2 = fmaxf(v2, 0.f); v3 = fmaxf(v3, 0.f);
            if (OUT == 1) {
                const size_t e0 = ((size_t)b2 * Mout + m0) * HW + hw;
                const size_t e1 = ((size_t)b2 * Mout + m1) * HW + hw;
                uint32_t h01 = pack_bf16x2(v0, v1);
                uint32_t l01 = pack_bf16x2(v0 - __uint_as_float(h01 << 16),
                                           v1 - __uint_as_float(h01 & 0xFFFF0000u));
                uint32_t h23 = pack_bf16x2(v2, v3);
                uint32_t l23 = pack_bf16x2(v2 - __uint_as_float(h23 << 16),
                                           v3 - __uint_as_float(h23 & 0xFFFF0000u));
                *(uint32_t*)(OutH + e0) = h01;
                *(uint32_t*)(OutL + e0) = l01;
                *(uint32_t*)(OutH + e1) = h23;
                *(uint32_t*)(OutL + e1) = l23;
            } else {
                *(float2*)(OutF + ((size_t)b2 * Mout + m0) * HW + hw) = make_float2(v0, v1);
                *(float2*)(OutF + ((size_t)b2 * Mout + m1) * HW + hw) = make_float2(v2, v3);
            }
        }
    }
}

// ---------------------------------------------------------------------------
// fp32 -> hi/lo bf16 split (pairwise, vectorized)
// ---------------------------------------------------------------------------
__global__ __launch_bounds__(256)
void cvt_split_kernel(const float* __restrict__ in, uint16_t* __restrict__ hi,
                      uint16_t* __restrict__ lo, long n2)
{
    long i = (long)blockIdx.x * blockDim.x + threadIdx.x;
    const long stride = (long)gridDim.x * blockDim.x;
    for (; i < n2; i += stride) {
        float2 v = ((const float2*)in)[i];
        uint32_t h = pack_bf16x2(v.x, v.y);
        uint32_t l = pack_bf16x2(v.x - __uint_as_float(h << 16),
                                 v.y - __uint_as_float(h & 0xFFFF0000u));
        ((uint32_t*)hi)[i] = h;
        ((uint32_t*)lo)[i] = l;
    }
}

// wd [co][ci][3][3] -> wdc [co][(kh*3+kw)*256 + ci], split hi/lo
__global__ __launch_bounds__(256)
void cvt_wd_kernel(const float* __restrict__ wd, uint16_t* __restrict__ hi,
                   uint16_t* __restrict__ lo)
{
    const long total = 256L * 2304;
    long o = (long)blockIdx.x * blockDim.x + threadIdx.x;
    const long stride = (long)gridDim.x * blockDim.x;
    for (; o < total; o += stride) {
        const int co = (int)(o / 2304);
        const int rr = (int)(o - (long)co * 2304);
        const int r  = rr >> 8;          // kh*3+kw
        const int ci = rr & 255;
        float v = wd[(size_t)co * 2304 + ci * 9 + r];
        uint32_t h = pack_bf16x2(v, 0.f);
        float hv = __uint_as_float(h << 16);
        uint32_t l = pack_bf16x2(v - hv, 0.f);
        hi[o] = (uint16_t)(h & 0xFFFFu);
        lo[o] = (uint16_t)(l & 0xFFFFu);
    }
}

// ---------------------------------------------------------------------------
// Fused shuffle + transpose + split: y1[b][c][perm[c][j]] -> y1t[b][j][c] hi/lo
// block = (jb, b): 28 j's x 256 c
// ---------------------------------------------------------------------------
__global__ __launch_bounds__(256)
void shuf_t_kernel(const float* __restrict__ y1, const int* __restrict__ perm,
                   uint16_t* __restrict__ outh, uint16_t* __restrict__ outl)
{
    __shared__ uint16_t sh[28][264];
    __shared__ uint16_t sl[28][264];
    const int tid = threadIdx.x, wid = tid >> 5, lane = tid & 31;
    const int b  = blockIdx.y;
    const int j0 = blockIdx.x * 28;

    // phase 1: gather + split + transpose into smem
    if (lane < 28) {
#pragma unroll 4
        for (int it = 0; it < 32; it++) {
            const int c = wid + it * 8;
            const int p = perm[(size_t)c * HW + j0 + lane];
            const float v = y1[((size_t)b * 256 + c) * HW + p];
            uint32_t h = pack_bf16x2(v, 0.f);
            float hv = __uint_as_float(h << 16);
            uint32_t l = pack_bf16x2(v - hv, 0.f);
            sh[lane][c] = (uint16_t)(h & 0xFFFFu);
            sl[lane][c] = (uint16_t)(l & 0xFFFFu);
        }
    }
    __syncthreads();

    // phase 2: coalesced writes (16B segs)
#pragma unroll
    for (int it = 0; it < 4; it++) {
        const int idx = tid + it * 256;
        if (idx < 28 * 32) {
            const int j = idx >> 5, s = idx & 31;
            const size_t e = ((size_t)b * HW + j0 + j) * 256 + s * 8;
            *(uint4*)(outh + e) = *(const uint4*)&sh[j][s * 8];
            *(uint4*)(outl + e) = *(const uint4*)&sl[j][s * 8];
        }
    }
}

// ---------------------------------------------------------------------------
extern "C" void kernel_launch(void* const* d_in, const int* in_sizes, int n_in,
                              void* d_out, int out_size)
{
    const float* x  = (const float*)d_in[0];   // [32,1024,28,28]
    const float* w1 = (const float*)d_in[1];   // [256,1024,1,1]
    const float* wd = (const float*)d_in[2];   // [256,256,3,3]
    const float* w3 = (const float*)d_in[3];   // [1024,256,1,1]
    const int*   pd = (const int*)d_in[4];     // [256,784]
    const int*   pr = (const int*)d_in[5];     // [1024,784]
    float*       out = (float*)d_out;          // [32,1024,28,28]

    float* y1;
    uint16_t *xh, *xl, *w1h, *w1l, *wdh, *wdl, *w3h, *w3l, *y1th, *y1tl, *y2h, *y2l;
    cudaGetSymbolAddress((void**)&y1,   g_y1);
    cudaGetSymbolAddress((void**)&xh,   g_xh);
    cudaGetSymbolAddress((void**)&xl,   g_xl);
    cudaGetSymbolAddress((void**)&w1h,  g_w1h);
    cudaGetSymbolAddress((void**)&w1l,  g_w1l);
    cudaGetSymbolAddress((void**)&wdh,  g_wdh);
    cudaGetSymbolAddress((void**)&wdl,  g_wdl);
    cudaGetSymbolAddress((void**)&w3h,  g_w3h);
    cudaGetSymbolAddress((void**)&w3l,  g_w3l);
    cudaGetSymbolAddress((void**)&y1th, g_y1th);
    cudaGetSymbolAddress((void**)&y1tl, g_y1tl);
    cudaGetSymbolAddress((void**)&y2h,  g_y2h);
    cudaGetSymbolAddress((void**)&y2l,  g_y2l);

    const int SM0 = 2 * 10240 * 2 + 2 * 2 * (32 * 272);    // MODE0: 75776
    const int SM1 = 2 * 10240 * 2 + 2 * 2 * (128 * 80);    // MODE1: 81920
    cudaFuncSetAttribute(conv_mma2<0, 0>, cudaFuncAttributeMaxDynamicSharedMemorySize, SM0);
    cudaFuncSetAttribute(conv_mma2<1, 1>, cudaFuncAttributeMaxDynamicSharedMemorySize, SM1);
    cudaFuncSetAttribute(conv_mma2<0, 2>, cudaFuncAttributeMaxDynamicSharedMemorySize, SM0);

    // 0) precompute: split x and weights to hi/lo bf16
    cvt_split_kernel<<<4736, 256>>>(x, xh, xl, 32L * 1024 * HW / 2);
    cvt_split_kernel<<<512, 256>>>(w1, w1h, w1l, 256L * 1024 / 2);
    cvt_split_kernel<<<512, 256>>>(w3, w3h, w3l, 1024L * 256 / 2);
    cvt_wd_kernel<<<1024, 256>>>(wd, wdh, wdl);

    // 1) conv1 (1x1, 1024->256) + relu -> y1 fp32
    {
        dim3 grid(NTOT / NT, 2);
        conv_mma2<0, 0><<<grid, 256, SM0>>>(w1h, w1l, xh, xl,
                                            y1, nullptr, nullptr, 256, 1024,
                                            nullptr, nullptr);
    }
    // 2) shuffle + transpose + split -> y1t hi/lo
    {
        dim3 grid(HW / 28, 32);
        shuf_t_kernel<<<grid, 256>>>(y1, pd, y1th, y1tl);
    }
    // 3) 3x3 conv (256->256, pad 1) + relu -> y2 hi/lo bf16
    {
        dim3 grid(NTOT / NT, 2);
        conv_mma2<1, 1><<<grid, 256, SM1>>>(wdh, wdl, y1th, y1tl,
                                            nullptr, y2h, y2l, 256, 2304,
                                            nullptr, nullptr);
    }
    // 4) conv3 (1x1, 256->1024) + shuffled residual + relu -> out
    {
        dim3 grid(NTOT / NT, 8);
        conv_mma2<0, 2><<<grid, 256, SM0>>>(w3h, w3l, y2h, y2l,
                                            out, nullptr, nullptr, 1024, 256,
                                            x, pr);
    }
}